// round 1
// baseline (speedup 1.0000x reference)
#include <cuda_runtime.h>

#define H 32
#define WPB 4          // warps (batch rows) per block
#define THREADS (WPB*32)

// ---------- packed f32x2 helpers (sm_103a dual FP32 pipe) ----------
__device__ __forceinline__ unsigned long long ffma2(unsigned long long a,
                                                    unsigned long long b,
                                                    unsigned long long c) {
    unsigned long long d;
    asm("fma.rn.f32x2 %0, %1, %2, %3;" : "=l"(d) : "l"(a), "l"(b), "l"(c));
    return d;
}
__device__ __forceinline__ float hsum2(unsigned long long a) {
    float lo, hi;
    asm("mov.b64 {%0, %1}, %2;" : "=f"(lo), "=f"(hi) : "l"(a));
    return lo + hi;
}
__device__ __forceinline__ float ex2f(float x) {
    float r; asm("ex2.approx.f32 %0, %1;" : "=f"(r) : "f"(x)); return r;
}
__device__ __forceinline__ float rcpf(float x) {
    float r; asm("rcp.approx.f32 %0, %1;" : "=f"(r) : "f"(x)); return r;
}
__device__ __forceinline__ float sigmoid_f(float a) {
    // 1/(1+e^-a) via ex2/rcp (rel err ~2^-22)
    float e = ex2f(-1.4426950408889634f * a);
    return rcpf(1.0f + e);
}
__device__ __forceinline__ float tanh_f(float a) {
    // (1 - e^-2a) / (1 + e^-2a); safe for |a| < ~40 (gate pre-acts are < ~10)
    float e = ex2f(-2.8853900817779268f * a);
    return (1.0f - e) * rcpf(1.0f + e);
}

// One warp = one batch row. lane = hidden unit index.
__global__ void __launch_bounds__(THREADS, 3)
gru_warp_kernel(const float* __restrict__ x,     // [B,T]
                const float* __restrict__ h0,    // [B,H]
                const float* __restrict__ W_ih,  // [3H] (I=1)
                const float* __restrict__ W_hh,  // [3H,H]
                const float* __restrict__ b_ih,  // [3H]
                const float* __restrict__ b_hh,  // [3H]
                const float* __restrict__ W_out, // [H]
                const float* __restrict__ b_out, // [1]
                float* __restrict__ y,           // [B,T]
                float* __restrict__ hn,          // [B,H]
                int B, int T)
{
    __shared__ __align__(16) float ring[WPB][2][H]; // double-buffered h broadcast
    __shared__ float hT[WPB][H][33];                // transposed 32-step history (pad 33)
    __shared__ float wout_s[H];

    const int lane = threadIdx.x & 31;
    const int w    = threadIdx.x >> 5;
    const int b    = blockIdx.x * WPB + w;

    if (threadIdx.x < H) wout_s[threadIdx.x] = W_out[threadIdx.x];
    __syncthreads();
    if (b >= B) return;

    // ---- preload recurrent weights for this lane's 3 gate rows, as f32 pairs ----
    unsigned long long Wr[16], Wz[16], Wn[16];
    {
        const unsigned long long* wr = (const unsigned long long*)(W_hh + (size_t)lane * H);
        const unsigned long long* wz = (const unsigned long long*)(W_hh + (size_t)(H + lane) * H);
        const unsigned long long* wn = (const unsigned long long*)(W_hh + (size_t)(2 * H + lane) * H);
        #pragma unroll
        for (int p = 0; p < 16; p++) { Wr[p] = wr[p]; Wz[p] = wz[p]; Wn[p] = wn[p]; }
    }
    const float wihr = W_ih[lane], wihz = W_ih[H + lane], wihn = W_ih[2 * H + lane];
    const float bsr  = b_ih[lane]        + b_hh[lane];          // r bias sum
    const float bsz  = b_ih[H + lane]    + b_hh[H + lane];      // z bias sum
    const float bin  = b_ih[2 * H + lane];                      // n: input-side bias
    const float bhn  = b_hh[2 * H + lane];                      // n: hidden-side bias (inside r*)
    const float bo   = b_out[0];

    float h = h0[(size_t)b * H + lane];
    ring[w][1][lane] = h;     // step 0 reads parity 1
    __syncwarp();

    const float* xrow = x + (size_t)b * T;
    float*       yrow = y + (size_t)b * T;

    for (int t0 = 0; t0 < T; t0 += 32) {
        const float xv = xrow[t0 + lane];   // 32 timesteps of input, coalesced

        #pragma unroll 4
        for (int s2 = 0; s2 < 32; s2 += 2) {
            #pragma unroll
            for (int ss = 0; ss < 2; ss++) {
                const int s  = s2 + ss;
                const int rd = (s & 1) ^ 1;   // read buffer (static after unroll)
                const int wb = (s & 1);       // write buffer

                const ulonglong2* hp = (const ulonglong2*)&ring[w][rd][0];
                unsigned long long ar = 0ull, az = 0ull, an = 0ull;
                #pragma unroll
                for (int q = 0; q < 8; q++) {
                    const ulonglong2 hv = hp[q];     // 4 h values = 2 packed pairs
                    ar = ffma2(hv.x, Wr[2 * q],     ar);
                    az = ffma2(hv.x, Wz[2 * q],     az);
                    an = ffma2(hv.x, Wn[2 * q],     an);
                    ar = ffma2(hv.y, Wr[2 * q + 1], ar);
                    az = ffma2(hv.y, Wz[2 * q + 1], az);
                    an = ffma2(hv.y, Wn[2 * q + 1], an);
                }
                const float xt = __shfl_sync(0xffffffffu, xv, s);
                const float gr = hsum2(ar);
                const float gz = hsum2(az);
                const float gn = hsum2(an);

                const float rg = sigmoid_f(fmaf(xt, wihr, bsr) + gr);
                const float zg = sigmoid_f(fmaf(xt, wihz, bsz) + gz);
                const float ng = tanh_f(fmaf(xt, wihn, bin) + rg * (gn + bhn));
                h = ng + zg * (h - ng);       // (1-z)*n + z*h

                ring[w][wb][lane] = h;        // broadcast for next step
                hT[w][lane][s]    = h;        // history for deferred y matvec
                __syncwarp();
            }
        }

        // deferred output: y[t0+lane] = dot(h_{t0+lane}, W_out) + b_out
        // lane reads hT[j][lane]: bank (33j+lane)%32 = (j+lane)%32 -> conflict-free
        float acc = bo;
        #pragma unroll
        for (int j = 0; j < H; j++)
            acc = fmaf(hT[w][j][lane], wout_s[j], acc);
        yrow[t0 + lane] = acc;                // coalesced
        __syncwarp();                          // hT reuse (WAR) next chunk
    }

    hn[(size_t)b * H + lane] = h;             // final state, coalesced
}

extern "C" void kernel_launch(void* const* d_in, const int* in_sizes, int n_in,
                              void* d_out, int out_size) {
    const float* x     = (const float*)d_in[0];   // [B,T,1]
    const float* h0    = (const float*)d_in[1];   // [1,B,H]
    const float* W_ih  = (const float*)d_in[2];   // [3H,1]
    const float* W_hh  = (const float*)d_in[3];   // [3H,H]
    const float* b_ih  = (const float*)d_in[4];   // [3H]
    const float* b_hh  = (const float*)d_in[5];   // [3H]
    const float* W_out = (const float*)d_in[6];   // [1,H]
    const float* b_out = (const float*)d_in[7];   // [1]
    float* out = (float*)d_out;

    const int B = in_sizes[1] / H;                // 2048
    const int T = in_sizes[0] / B;                // 1024

    float* y  = out;                              // [B,T]
    float* hn = out + (size_t)B * T;              // [B,H]

    const int grid = (B + WPB - 1) / WPB;
    gru_warp_kernel<<<grid, THREADS>>>(x, h0, W_ih, W_hh, b_ih, b_hh,
                                       W_out, b_out, y, hn, B, T);
}

// round 2
// speedup vs baseline: 1.0901x; 1.0901x over previous
#include <cuda_runtime.h>

#define H 32
#define WPB 16         // warps (batch rows) per block
#define THREADS (WPB*32)
#define CHUNK 16       // deferred-output chunk (keeps hT under 48KB static smem)

// ---------- packed f32x2 helpers (sm_103a dual FP32 pipe) ----------
__device__ __forceinline__ unsigned long long ffma2(unsigned long long a,
                                                    unsigned long long b,
                                                    unsigned long long c) {
    unsigned long long d;
    asm("fma.rn.f32x2 %0, %1, %2, %3;" : "=l"(d) : "l"(a), "l"(b), "l"(c));
    return d;
}
__device__ __forceinline__ float hsum2(unsigned long long a) {
    float lo, hi;
    asm("mov.b64 {%0, %1}, %2;" : "=f"(lo), "=f"(hi) : "l"(a));
    return lo + hi;
}
__device__ __forceinline__ float ex2f(float x) {
    float r; asm("ex2.approx.f32 %0, %1;" : "=f"(r) : "f"(x)); return r;
}
__device__ __forceinline__ float rcpf(float x) {
    float r; asm("rcp.approx.f32 %0, %1;" : "=f"(r) : "f"(x)); return r;
}
__device__ __forceinline__ float sigmoid_f(float a) {
    float e = ex2f(-1.4426950408889634f * a);
    return rcpf(1.0f + e);
}
__device__ __forceinline__ float tanh_f(float a) {
    // tanh(a) = 2/(1+e^-2a) - 1 ; FFMA with immediates is rt=1 on sm_103a
    float e = ex2f(-2.8853900817779268f * a);
    return fmaf(2.0f, rcpf(1.0f + e), -1.0f);
}

// One warp = one batch row. lane = hidden unit index. 16 warps/block,
// grid=128 -> exactly one block per SM, single wave, perfect balance.
__global__ void __launch_bounds__(THREADS, 1)
gru_warp_kernel(const float* __restrict__ x,     // [B,T]
                const float* __restrict__ h0,    // [B,H]
                const float* __restrict__ W_ih,  // [3H] (I=1)
                const float* __restrict__ W_hh,  // [3H,H]
                const float* __restrict__ b_ih,  // [3H]
                const float* __restrict__ b_hh,  // [3H]
                const float* __restrict__ W_out, // [H]
                const float* __restrict__ b_out, // [1]
                float* __restrict__ y,           // [B,T]
                float* __restrict__ hn,          // [B,H]
                int B, int T)
{
    __shared__ __align__(16) float ring[WPB][2][H];      // double-buffered h broadcast
    __shared__ float hT[WPB][H][CHUNK + 1];              // transposed step history (pad 17)
    __shared__ float wout_s[H];

    const int lane = threadIdx.x & 31;
    const int w    = threadIdx.x >> 5;
    const int b    = blockIdx.x * WPB + w;

    if (threadIdx.x < H) wout_s[threadIdx.x] = W_out[threadIdx.x];
    __syncthreads();
    if (b >= B) return;

    // ---- recurrent weights for this lane's 3 gate rows, packed as f32 pairs ----
    unsigned long long Wr[16], Wz[16], Wn[16];
    {
        const unsigned long long* wr = (const unsigned long long*)(W_hh + (size_t)lane * H);
        const unsigned long long* wz = (const unsigned long long*)(W_hh + (size_t)(H + lane) * H);
        const unsigned long long* wn = (const unsigned long long*)(W_hh + (size_t)(2 * H + lane) * H);
        #pragma unroll
        for (int p = 0; p < 16; p++) { Wr[p] = wr[p]; Wz[p] = wz[p]; Wn[p] = wn[p]; }
    }
    const float wihr = W_ih[lane], wihz = W_ih[H + lane], wihn = W_ih[2 * H + lane];
    const float bsr  = b_ih[lane]        + b_hh[lane];
    const float bsz  = b_ih[H + lane]    + b_hh[H + lane];
    const float bin  = b_ih[2 * H + lane];
    const float bhn  = b_hh[2 * H + lane];
    const float bo   = b_out[0];

    float h = h0[(size_t)b * H + lane];
    ring[w][1][lane] = h;     // step 0 reads parity 1
    __syncwarp();

    const float* xrow = x + (size_t)b * T;
    float*       yrow = y + (size_t)b * T;

    // y-reduction lane roles (constant per thread)
    const int tloc = lane & 15;          // which timestep of the chunk this lane finishes
    const int jb   = lane & 16;          // which half of H this lane accumulates

    for (int t0 = 0; t0 < T; t0 += CHUNK) {
        // 16 timesteps of input staged in lanes 0..15 (dup in 16..31), 64B coalesced
        const float xv = xrow[t0 + tloc];

        #pragma unroll 2
        for (int s = 0; s < CHUNK; s++) {
            const int rd = (s & 1) ^ 1;
            const int wb = (s & 1);

            const ulonglong2* hp = (const ulonglong2*)&ring[w][rd][0];
            unsigned long long ar = 0ull, az = 0ull, an = 0ull;
            #pragma unroll
            for (int q = 0; q < 8; q++) {
                const ulonglong2 hv = hp[q];      // 4 h values = 2 packed pairs
                ar = ffma2(hv.x, Wr[2 * q],     ar);
                az = ffma2(hv.x, Wz[2 * q],     az);
                an = ffma2(hv.x, Wn[2 * q],     an);
                ar = ffma2(hv.y, Wr[2 * q + 1], ar);
                az = ffma2(hv.y, Wz[2 * q + 1], az);
                an = ffma2(hv.y, Wn[2 * q + 1], an);
            }
            const float xt = __shfl_sync(0xffffffffu, xv, s);
            const float gr = hsum2(ar);
            const float gz = hsum2(az);
            const float gn = hsum2(an);

            const float rg = sigmoid_f(fmaf(xt, wihr, bsr) + gr);
            const float zg = sigmoid_f(fmaf(xt, wihz, bsz) + gz);
            const float ng = tanh_f(fmaf(xt, wihn, bin) + rg * (gn + bhn));
            h = fmaf(zg, h - ng, ng);             // (1-z)*n + z*h

            ring[w][wb][lane] = h;                // broadcast for next step
            hT[w][lane][s]    = h;                // history for deferred y matvec
            __syncwarp();
        }

        // Deferred output for 16 steps, split across half-warps:
        //   lanes 0..15  accumulate j=0..15  for timestep tloc
        //   lanes 16..31 accumulate j=16..31 for timestep tloc
        // hT banks: addr 17*j + tloc -> all 32 lanes hit distinct banks.
        float acc = 0.0f;
        #pragma unroll
        for (int k = 0; k < 16; k++)
            acc = fmaf(hT[w][jb + k][tloc], wout_s[jb + k], acc);
        acc += __shfl_xor_sync(0xffffffffu, acc, 16);
        if (lane < 16) yrow[t0 + lane] = acc + bo;   // 64B coalesced
        __syncwarp();                                 // hT WAR before next chunk
    }

    hn[(size_t)b * H + lane] = h;
}

extern "C" void kernel_launch(void* const* d_in, const int* in_sizes, int n_in,
                              void* d_out, int out_size) {
    const float* x     = (const float*)d_in[0];   // [B,T,1]
    const float* h0    = (const float*)d_in[1];   // [1,B,H]
    const float* W_ih  = (const float*)d_in[2];   // [3H,1]
    const float* W_hh  = (const float*)d_in[3];   // [3H,H]
    const float* b_ih  = (const float*)d_in[4];   // [3H]
    const float* b_hh  = (const float*)d_in[5];   // [3H]
    const float* W_out = (const float*)d_in[6];   // [1,H]
    const float* b_out = (const float*)d_in[7];   // [1]
    float* out = (float*)d_out;

    const int B = in_sizes[1] / H;                // 2048
    const int T = in_sizes[0] / B;                // 1024

    float* y  = out;                              // [B,T]
    float* hn = out + (size_t)B * T;              // [B,H]

    const int grid = (B + WPB - 1) / WPB;         // 128
    gru_warp_kernel<<<grid, THREADS>>>(x, h0, W_ih, W_hh, b_ih, b_hh,
                                       W_out, b_out, y, hn, B, T);
}

// round 3
// speedup vs baseline: 1.2995x; 1.1920x over previous
#include <cuda_runtime.h>

#define H 32
#define WPB 16         // warps (batch rows) per block
#define THREADS (WPB*32)
#define CHUNK 16       // deferred-output chunk

// ---------- packed f32x2 helpers (sm_103a dual FP32 pipe) ----------
__device__ __forceinline__ unsigned long long ffma2(unsigned long long a,
                                                    unsigned long long b,
                                                    unsigned long long c) {
    unsigned long long d;
    asm("fma.rn.f32x2 %0, %1, %2, %3;" : "=l"(d) : "l"(a), "l"(b), "l"(c));
    return d;
}
__device__ __forceinline__ unsigned long long addf2(unsigned long long a,
                                                    unsigned long long b) {
    unsigned long long d;
    asm("add.rn.f32x2 %0, %1, %2;" : "=l"(d) : "l"(a), "l"(b));
    return d;
}
__device__ __forceinline__ unsigned long long mulf2(unsigned long long a,
                                                    unsigned long long b) {
    unsigned long long d;
    asm("mul.rn.f32x2 %0, %1, %2;" : "=l"(d) : "l"(a), "l"(b));
    return d;
}
__device__ __forceinline__ float hsum2(unsigned long long a) {
    float lo, hi;
    asm("mov.b64 {%0, %1}, %2;" : "=f"(lo), "=f"(hi) : "l"(a));
    return lo + hi;
}
__device__ __forceinline__ float tanh_ap(float x) {
    float r; asm("tanh.approx.f32 %0, %1;" : "=f"(r) : "f"(x)); return r;
}

// One warp = one batch row. lane = hidden unit. grid=128 -> 1 block/SM, 1 wave.
__global__ void __launch_bounds__(THREADS, 1)
gru_warp_kernel(const float* __restrict__ x,     // [B,T]
                const float* __restrict__ h0,    // [B,H]
                const float* __restrict__ W_ih,  // [3H] (I=1)
                const float* __restrict__ W_hh,  // [3H,H]
                const float* __restrict__ b_ih,  // [3H]
                const float* __restrict__ b_hh,  // [3H]
                const float* __restrict__ W_out, // [H]
                const float* __restrict__ b_out, // [1]
                float* __restrict__ y,           // [B,T]
                float* __restrict__ hn,          // [B,H]
                int B, int T)
{
    __shared__ __align__(16) float ring[WPB][2][H];      // double-buffered h broadcast
    __shared__ float hT[WPB][H][CHUNK + 1];              // transposed step history
    __shared__ float wout_s[H];

    const int lane = threadIdx.x & 31;
    const int w    = threadIdx.x >> 5;
    const int b    = blockIdx.x * WPB + w;

    if (threadIdx.x < H) wout_s[threadIdx.x] = W_out[threadIdx.x];
    __syncthreads();
    if (b >= B) return;

    // ---- recurrent weights, packed pairs. r/z rows pre-scaled by 0.5 so that
    //      sigmoid(a) = 0.5 + 0.5*tanh(a/2) costs one trailing FFMA-imm. ----
    unsigned long long Wr[16], Wz[16], Wn[16];
    {
        const unsigned long long HALF2 = 0x3F0000003F000000ull;  // (0.5f, 0.5f)
        const unsigned long long* wr = (const unsigned long long*)(W_hh + (size_t)lane * H);
        const unsigned long long* wz = (const unsigned long long*)(W_hh + (size_t)(H + lane) * H);
        const unsigned long long* wn = (const unsigned long long*)(W_hh + (size_t)(2 * H + lane) * H);
        #pragma unroll
        for (int p = 0; p < 16; p++) {
            Wr[p] = mulf2(wr[p], HALF2);
            Wz[p] = mulf2(wz[p], HALF2);
            Wn[p] = wn[p];
        }
    }
    const float wihr = 0.5f * W_ih[lane];
    const float wihz = 0.5f * W_ih[H + lane];
    const float wihn = W_ih[2 * H + lane];
    const float bsr  = 0.5f * (b_ih[lane]     + b_hh[lane]);
    const float bsz  = 0.5f * (b_ih[H + lane] + b_hh[H + lane]);
    const float bin  = b_ih[2 * H + lane];
    const float bhn  = b_hh[2 * H + lane];
    const float bo   = b_out[0];

    float h = h0[(size_t)b * H + lane];
    ring[w][1][lane] = h;     // step 0 reads parity 1
    __syncwarp();

    const float* xrow = x + (size_t)b * T;
    float*       yrow = y + (size_t)b * T;

    const int tloc = lane & 15;          // timestep this lane finishes in y-phase
    const int jb   = lane & 16;          // which half of H this lane accumulates

    for (int t0 = 0; t0 < T; t0 += CHUNK) {
        const float xv = xrow[t0 + tloc];      // 16 steps of input, 64B coalesced

        #pragma unroll 2
        for (int s = 0; s < CHUNK; s++) {
            const int rd = (s & 1) ^ 1;
            const int wb = (s & 1);

            const float xt = __shfl_sync(0xffffffffu, xv, s);  // issue early

            const ulonglong2* hp = (const ulonglong2*)&ring[w][rd][0];
            // split accumulators: halves the serial FFMA2 chain (16 -> 8 deps)
            unsigned long long ar0 = 0ull, ar1 = 0ull;
            unsigned long long az0 = 0ull, az1 = 0ull;
            unsigned long long an0 = 0ull, an1 = 0ull;
            #pragma unroll
            for (int q = 0; q < 8; q++) {
                const ulonglong2 hv = hp[q];
                ar0 = ffma2(hv.x, Wr[2 * q],     ar0);
                az0 = ffma2(hv.x, Wz[2 * q],     az0);
                an0 = ffma2(hv.x, Wn[2 * q],     an0);
                ar1 = ffma2(hv.y, Wr[2 * q + 1], ar1);
                az1 = ffma2(hv.y, Wz[2 * q + 1], az1);
                an1 = ffma2(hv.y, Wn[2 * q + 1], an1);
            }
            const float gr = hsum2(addf2(ar0, ar1));
            const float gz = hsum2(addf2(az0, az1));
            const float gn = hsum2(addf2(an0, an1));

            const float tr = tanh_ap(fmaf(xt, wihr, bsr) + gr);
            const float tz = tanh_ap(fmaf(xt, wihz, bsz) + gz);
            const float rg = fmaf(0.5f, tr, 0.5f);             // sigmoid(r)
            const float zg = fmaf(0.5f, tz, 0.5f);             // sigmoid(z)
            const float ng = tanh_ap(fmaf(xt, wihn, bin) + rg * (gn + bhn));
            h = fmaf(zg, h - ng, ng);                          // (1-z)*n + z*h

            ring[w][wb][lane] = h;
            hT[w][lane][s]    = h;
            __syncwarp();
        }

        // Deferred y: half-warp split reduction, conflict-free (stride 17)
        float acc = 0.0f;
        #pragma unroll
        for (int k = 0; k < 16; k++)
            acc = fmaf(hT[w][jb + k][tloc], wout_s[jb + k], acc);
        acc += __shfl_xor_sync(0xffffffffu, acc, 16);
        if (lane < 16) yrow[t0 + lane] = acc + bo;
        __syncwarp();
    }

    hn[(size_t)b * H + lane] = h;
}

extern "C" void kernel_launch(void* const* d_in, const int* in_sizes, int n_in,
                              void* d_out, int out_size) {
    const float* x     = (const float*)d_in[0];   // [B,T,1]
    const float* h0    = (const float*)d_in[1];   // [1,B,H]
    const float* W_ih  = (const float*)d_in[2];   // [3H,1]
    const float* W_hh  = (const float*)d_in[3];   // [3H,H]
    const float* b_ih  = (const float*)d_in[4];   // [3H]
    const float* b_hh  = (const float*)d_in[5];   // [3H]
    const float* W_out = (const float*)d_in[6];   // [1,H]
    const float* b_out = (const float*)d_in[7];   // [1]
    float* out = (float*)d_out;

    const int B = in_sizes[1] / H;                // 2048
    const int T = in_sizes[0] / B;                // 1024

    float* y  = out;                              // [B,T]
    float* hn = out + (size_t)B * T;              // [B,H]

    const int grid = (B + WPB - 1) / WPB;         // 128
    gru_warp_kernel<<<grid, THREADS>>>(x, h0, W_ih, W_hh, b_ih, b_hh,
                                       W_out, b_out, y, hn, B, T);
}

// round 4
// speedup vs baseline: 1.4231x; 1.0951x over previous
#include <cuda_runtime.h>

#define H 32
#define WPB 7           // warps per block; each warp = 2 batch rows
#define THREADS (WPB*32)
#define CHUNK 16        // deferred-output chunk
#define RSTRIDE 48      // ring row stride (floats): 16-bank shift between rows
#define TSTRIDE 560     // hT row stride (floats): 560%32==16 -> bank shift

typedef unsigned long long ull;

// ---------- packed f32x2 helpers (sm_103a dual FP32 pipe) ----------
__device__ __forceinline__ ull ffma2(ull a, ull b, ull c) {
    ull d;
    asm("fma.rn.f32x2 %0, %1, %2, %3;" : "=l"(d) : "l"(a), "l"(b), "l"(c));
    return d;
}
__device__ __forceinline__ ull mulf2(ull a, ull b) {
    ull d;
    asm("mul.rn.f32x2 %0, %1, %2;" : "=l"(d) : "l"(a), "l"(b));
    return d;
}
__device__ __forceinline__ float hsum2(ull a) {
    float lo, hi;
    asm("mov.b64 {%0, %1}, %2;" : "=f"(lo), "=f"(hi) : "l"(a));
    return lo + hi;
}
__device__ __forceinline__ float tanh_ap(float x) {
    float r; asm("tanh.approx.f32 %0, %1;" : "=f"(r) : "f"(x)); return r;
}

// One warp = 2 batch rows (half-warp per row); lane owns hidden units u0, u0+16
// of its row. grid=147 x 7 warps covers 1024 row-pairs, single wave, all SMs.
__global__ void __launch_bounds__(THREADS, 1)
gru_warp_kernel(const float* __restrict__ x,     // [B,T]
                const float* __restrict__ h0,    // [B,H]
                const float* __restrict__ W_ih,  // [3H] (I=1)
                const float* __restrict__ W_hh,  // [3H,H]
                const float* __restrict__ b_ih,  // [3H]
                const float* __restrict__ b_hh,  // [3H]
                const float* __restrict__ W_out, // [H]
                const float* __restrict__ b_out, // [1]
                float* __restrict__ y,           // [B,T]
                float* __restrict__ hn,          // [B,H]
                int B, int T)
{
    __shared__ __align__(16) float ring[WPB][2][2 * RSTRIDE]; // double-buffered h, 2 rows
    __shared__ float hT[WPB][2][TSTRIDE];                     // per-row 32x17 history
    __shared__ float wout_s[H];

    const int lane = threadIdx.x & 31;
    const int w    = threadIdx.x >> 5;
    const int npairs = B >> 1;
    const int p    = blockIdx.x * WPB + w;

    if (threadIdx.x < H) wout_s[threadIdx.x] = W_out[threadIdx.x];
    __syncthreads();
    if (p >= npairs) return;

    const int u0  = lane & 15;     // first hidden unit this lane owns
    const int r   = lane >> 4;     // which row of the pair this half-warp runs
    const int row = 2 * p + r;     // global batch row

    // ---- recurrent weights for units u0 and u0+16 (6 gate rows), packed pairs.
    //      r/z rows pre-scaled by 0.5: sigmoid(a) = 0.5 + 0.5*tanh(a/2). ----
    ull Wr0[16], Wz0[16], Wn0[16], Wr1[16], Wz1[16], Wn1[16];
    {
        const ull HALF2 = 0x3F0000003F000000ull;  // (0.5f, 0.5f)
        const int u1 = u0 + 16;
        const ull* wr0 = (const ull*)(W_hh + (size_t)u0 * H);
        const ull* wz0 = (const ull*)(W_hh + (size_t)(H + u0) * H);
        const ull* wn0 = (const ull*)(W_hh + (size_t)(2 * H + u0) * H);
        const ull* wr1 = (const ull*)(W_hh + (size_t)u1 * H);
        const ull* wz1 = (const ull*)(W_hh + (size_t)(H + u1) * H);
        const ull* wn1 = (const ull*)(W_hh + (size_t)(2 * H + u1) * H);
        #pragma unroll
        for (int k = 0; k < 16; k++) {
            Wr0[k] = mulf2(wr0[k], HALF2);
            Wz0[k] = mulf2(wz0[k], HALF2);
            Wn0[k] = wn0[k];
            Wr1[k] = mulf2(wr1[k], HALF2);
            Wz1[k] = mulf2(wz1[k], HALF2);
            Wn1[k] = wn1[k];
        }
    }
    const int u1 = u0 + 16;
    const float wihr0 = 0.5f * W_ih[u0],  wihr1 = 0.5f * W_ih[u1];
    const float wihz0 = 0.5f * W_ih[H + u0], wihz1 = 0.5f * W_ih[H + u1];
    const float wihn0 = W_ih[2 * H + u0], wihn1 = W_ih[2 * H + u1];
    const float bsr0  = 0.5f * (b_ih[u0] + b_hh[u0]);
    const float bsr1  = 0.5f * (b_ih[u1] + b_hh[u1]);
    const float bsz0  = 0.5f * (b_ih[H + u0] + b_hh[H + u0]);
    const float bsz1  = 0.5f * (b_ih[H + u1] + b_hh[H + u1]);
    const float bin0  = b_ih[2 * H + u0], bin1 = b_ih[2 * H + u1];
    // n-gate hidden bias folded into accumulator init (lo half of packed pair)
    const ull an_init0 = (ull)__float_as_uint(b_hh[2 * H + u0]);
    const ull an_init1 = (ull)__float_as_uint(b_hh[2 * H + u1]);
    const float bo = b_out[0];

    float hA = h0[(size_t)row * H + u0];
    float hB = h0[(size_t)row * H + u1];
    ring[w][1][r * RSTRIDE + u0] = hA;     // step 0 reads parity 1
    ring[w][1][r * RSTRIDE + u1] = hB;
    __syncwarp();

    const float* xrow = x + (size_t)row * T;
    float*       yrow = y + (size_t)row * T;
    float* hTrow = &hT[w][r][0];

    for (int t0 = 0; t0 < T; t0 += CHUNK) {
        const float xv = xrow[t0 + u0];   // lane tloc==u0 stages this row's inputs

        #pragma unroll 2
        for (int s = 0; s < CHUNK; s++) {
            const int rd = (s & 1) ^ 1;
            const int wb = (s & 1);

            const float xt = __shfl_sync(0xffffffffu, xv, s, 16); // per-half bcast

            const ulonglong2* hp = (const ulonglong2*)&ring[w][rd][r * RSTRIDE];
            ull ar0 = 0ull, az0 = 0ull, an0 = an_init0;
            ull ar1 = 0ull, az1 = 0ull, an1 = an_init1;
            #pragma unroll
            for (int q = 0; q < 8; q++) {
                const ulonglong2 hv = hp[q];     // 4 h values of this row
                ar0 = ffma2(hv.x, Wr0[2 * q],     ar0);
                az0 = ffma2(hv.x, Wz0[2 * q],     az0);
                an0 = ffma2(hv.x, Wn0[2 * q],     an0);
                ar1 = ffma2(hv.x, Wr1[2 * q],     ar1);
                az1 = ffma2(hv.x, Wz1[2 * q],     az1);
                an1 = ffma2(hv.x, Wn1[2 * q],     an1);
                ar0 = ffma2(hv.y, Wr0[2 * q + 1], ar0);
                az0 = ffma2(hv.y, Wz0[2 * q + 1], az0);
                an0 = ffma2(hv.y, Wn0[2 * q + 1], an0);
                ar1 = ffma2(hv.y, Wr1[2 * q + 1], ar1);
                az1 = ffma2(hv.y, Wz1[2 * q + 1], az1);
                an1 = ffma2(hv.y, Wn1[2 * q + 1], an1);
            }
            // unit u0
            {
                const float tr = tanh_ap(fmaf(xt, wihr0, bsr0 + hsum2(ar0)));
                const float tz = tanh_ap(fmaf(xt, wihz0, bsz0 + hsum2(az0)));
                const float rg = fmaf(0.5f, tr, 0.5f);
                const float zg = fmaf(0.5f, tz, 0.5f);
                const float ng = tanh_ap(fmaf(rg, hsum2(an0),
                                              fmaf(xt, wihn0, bin0)));
                hA = fmaf(zg, hA - ng, ng);
            }
            // unit u0+16
            {
                const float tr = tanh_ap(fmaf(xt, wihr1, bsr1 + hsum2(ar1)));
                const float tz = tanh_ap(fmaf(xt, wihz1, bsz1 + hsum2(az1)));
                const float rg = fmaf(0.5f, tr, 0.5f);
                const float zg = fmaf(0.5f, tz, 0.5f);
                const float ng = tanh_ap(fmaf(rg, hsum2(an1),
                                              fmaf(xt, wihn1, bin1)));
                hB = fmaf(zg, hB - ng, ng);
            }

            ring[w][wb][r * RSTRIDE + u0] = hA;
            ring[w][wb][r * RSTRIDE + u1] = hB;
            hTrow[17 * u0 + s] = hA;          // conflict-free (derived bank map)
            hTrow[17 * u1 + s] = hB;
            __syncwarp();
        }

        // Deferred y: every lane produces one output (row r, timestep u0).
        float acc = 0.0f;
        #pragma unroll
        for (int j = 0; j < H; j++)
            acc = fmaf(hTrow[17 * j + u0], wout_s[j], acc);
        yrow[t0 + u0] = acc + bo;             // 2x64B coalesced, all lanes
        __syncwarp();                          // hT WAR before next chunk
    }

    hn[(size_t)row * H + u0] = hA;
    hn[(size_t)row * H + u1] = hB;
}

extern "C" void kernel_launch(void* const* d_in, const int* in_sizes, int n_in,
                              void* d_out, int out_size) {
    const float* x     = (const float*)d_in[0];   // [B,T,1]
    const float* h0    = (const float*)d_in[1];   // [1,B,H]
    const float* W_ih  = (const float*)d_in[2];   // [3H,1]
    const float* W_hh  = (const float*)d_in[3];   // [3H,H]
    const float* b_ih  = (const float*)d_in[4];   // [3H]
    const float* b_hh  = (const float*)d_in[5];   // [3H]
    const float* W_out = (const float*)d_in[6];   // [1,H]
    const float* b_out = (const float*)d_in[7];   // [1]
    float* out = (float*)d_out;

    const int B = in_sizes[1] / H;                // 2048
    const int T = in_sizes[0] / B;                // 1024

    float* y  = out;                              // [B,T]
    float* hn = out + (size_t)B * T;              // [B,H]

    const int npairs = B / 2;                     // 1024
    const int grid = (npairs + WPB - 1) / WPB;    // 147 -> all SMs, single wave
    gru_warp_kernel<<<grid, THREADS>>>(x, h0, W_ih, W_hh, b_ih, b_hh,
                                       W_out, b_out, y, hn, B, T);
}